// round 2
// baseline (speedup 1.0000x reference)
#include <cuda_runtime.h>
#include <math.h>

#define NN   50000
#define EE   800000
#define DIN  64
#define DH   128
#define DOUT 10
#define EPS  1e-8f

// ---------------- scratch ----------------
__device__ int   g_degi[NN];
__device__ float g_deg[NN];
__device__ int   g_rowptr[NN + 1];
__device__ int   g_cursor[NN];
__device__ int   g_csrsrc[EE];
__device__ float g_s[NN * DOUT];
__device__ float g_t[NN * DOUT];
__device__ float g_agg1[NN * DOUT];

// ---------------- CSR build ----------------
__global__ void zero_deg_kernel() {
    int i = blockIdx.x * blockDim.x + threadIdx.x;
    if (i < NN) g_degi[i] = 0;
}

__global__ void count_kernel(const int* __restrict__ dst) {
    int e = blockIdx.x * blockDim.x + threadIdx.x;
    if (e < EE) atomicAdd(&g_degi[dst[e]], 1);
}

__global__ void scan_kernel() {
    __shared__ int warp_sums[32];
    const int T = 1024;
    int tid = threadIdx.x;
    int per = (NN + T - 1) / T;
    int start = tid * per;
    int end = start + per; if (end > NN) end = NN;
    int local = 0;
    if (start < NN)
        for (int i = start; i < end; i++) local += g_degi[i];

    int lane = tid & 31, wid = tid >> 5;
    int v = local;
    #pragma unroll
    for (int o = 1; o < 32; o <<= 1) {
        int u = __shfl_up_sync(0xFFFFFFFFu, v, o);
        if (lane >= o) v += u;
    }
    if (lane == 31) warp_sums[wid] = v;
    __syncthreads();
    if (wid == 0) {
        int w = warp_sums[lane];
        #pragma unroll
        for (int o = 1; o < 32; o <<= 1) {
            int u = __shfl_up_sync(0xFFFFFFFFu, w, o);
            if (lane >= o) w += u;
        }
        warp_sums[lane] = w;
    }
    __syncthreads();
    int excl = v - local + (wid > 0 ? warp_sums[wid - 1] : 0);
    if (start < NN) {
        int run = excl;
        for (int i = start; i < end; i++) {
            g_rowptr[i] = run;
            g_cursor[i] = run;
            g_deg[i] = (float)g_degi[i];
            run += g_degi[i];
        }
    }
    if (tid == 0) g_rowptr[NN] = warp_sums[31];
}

__global__ void fill_kernel(const int* __restrict__ src, const int* __restrict__ dst) {
    int e = blockIdx.x * blockDim.x + threadIdx.x;
    if (e < EE) {
        int d = dst[e];
        int p = atomicAdd(&g_cursor[d], 1);
        g_csrsrc[p] = src[e];
    }
}

// ---------------- fused: gather + layer0 transform + norm/relu + layer1 projections ----
// block = node, 128 threads (4 warps)
__global__ void __launch_bounds__(128) fused0_kernel(
    const float* __restrict__ x,
    const float* __restrict__ Ws0,   // (65,128)
    const float* __restrict__ Wn0,   // (65,128)
    const float* __restrict__ Ws1,   // (129,10)
    const float* __restrict__ Wn1)   // (129,10)
{
    __shared__ int   sh_idx[128];
    __shared__ float sh_self[DIN + 1];
    __shared__ float sh_neigh[DIN + 1];
    __shared__ float sh_acc[4 * DIN];
    __shared__ float sh_h[DH];
    __shared__ float red[4];

    int node = blockIdx.x;
    int tid  = threadIdx.x;
    int lane = tid & 31;
    int wid  = tid >> 5;

    int beg = g_rowptr[node];
    int deg = g_rowptr[node + 1] - beg;

    // self row -> shared (independent of gather)
    if (tid < DIN) sh_self[tid] = x[(size_t)node * DIN + tid];
    if (tid == 0) sh_self[DIN] = 1.f;

    // ---- gather: 4 warps split the edge list, lane handles 2 feats ----
    float a0 = 0.f, a1 = 0.f;
    for (int base = 0; base < deg; base += 128) {
        int c = deg - base; if (c > 128) c = 128;
        __syncthreads();
        if (tid < c) sh_idx[tid] = g_csrsrc[beg + base + tid];
        __syncthreads();
        for (int e = wid; e < c; e += 4) {
            int s = sh_idx[e];
            float2 v = *(const float2*)(x + (size_t)s * DIN + lane * 2);
            a0 += v.x; a1 += v.y;
        }
    }
    sh_acc[wid * DIN + lane * 2]     = a0;
    sh_acc[wid * DIN + lane * 2 + 1] = a1;
    __syncthreads();

    float degv = (float)deg;
    float inv = 1.f / fmaxf(degv, 1.f);
    if (tid < DIN) {
        float ns = sh_acc[tid] + sh_acc[DIN + tid] + sh_acc[2 * DIN + tid] + sh_acc[3 * DIN + tid];
        sh_neigh[tid] = ns * inv;
    }
    if (tid == 0) sh_neigh[DIN] = (deg > 0) ? 1.f : 0.f;
    __syncthreads();

    // ---- layer-0 transform: thread = output column ----
    float acc = 0.f;
    #pragma unroll 13
    for (int k = 0; k < DIN + 1; k++) {
        acc += sh_self[k]  * Ws0[k * DH + tid];
        acc += sh_neigh[k] * Wn0[k * DH + tid];
    }
    float sq = acc * acc;
    #pragma unroll
    for (int o = 16; o > 0; o >>= 1) sq += __shfl_xor_sync(0xFFFFFFFFu, sq, o);
    if (lane == 0) red[wid] = sq;
    __syncthreads();
    float tot = red[0] + red[1] + red[2] + red[3];
    float h = fmaxf(acc / (sqrtf(tot) + EPS), 0.f);   // relu(normalized)
    sh_h[tid] = h;
    __syncthreads();

    // ---- layer-1 projections: 20 dots of length 128, 5 per warp ----
    // outputs 0..9 -> s (W_self1), 10..19 -> t (W_neigh1)
    float p[5];
    #pragma unroll
    for (int q = 0; q < 5; q++) {
        int j20 = wid * 5 + q;
        const float* W = (j20 < 10) ? Ws1 : Wn1;
        int col = (j20 < 10) ? j20 : (j20 - 10);
        float pp = 0.f;
        #pragma unroll
        for (int m = 0; m < 4; m++) {
            int k = lane + 32 * m;
            pp += sh_h[k] * W[k * DOUT + col];
        }
        p[q] = pp;
    }
    #pragma unroll
    for (int q = 0; q < 5; q++) {
        #pragma unroll
        for (int o = 16; o > 0; o >>= 1)
            p[q] += __shfl_xor_sync(0xFFFFFFFFu, p[q], o);
    }
    if (lane == 0) {
        #pragma unroll
        for (int q = 0; q < 5; q++) {
            int j20 = wid * 5 + q;
            if (j20 < 10)
                g_s[node * DOUT + j20] = p[q] + Ws1[DH * DOUT + j20];  // + homogeneous bias
            else
                g_t[node * DOUT + (j20 - 10)] = p[q];
        }
    }
}

// ---------------- layer 1 aggregation in output space (10 feats) ----------------
__global__ void agg1_kernel() {
    int idx = blockIdx.x * blockDim.x + threadIdx.x;
    if (idx >= NN * DOUT) return;
    int node = idx / DOUT;
    int j = idx - node * DOUT;
    int beg = g_rowptr[node], end = g_rowptr[node + 1];
    float acc = 0.f;
    for (int p = beg; p < end; p++) {
        int s = g_csrsrc[p];
        acc += g_t[s * DOUT + j];
    }
    g_agg1[idx] = acc;
}

// ---------------- final: combine, projective norm, log-softmax ----------------
__global__ void final_kernel(const float* __restrict__ Wn1, float* __restrict__ out) {
    int node = blockIdx.x * blockDim.x + threadIdx.x;
    if (node >= NN) return;
    float degv = g_deg[node];
    float inv = 1.f / fmaxf(degv, 1.f);
    float ind = (degv > 0.f) ? 1.f : 0.f;
    float v[DOUT];
    float nrm = 0.f;
    #pragma unroll
    for (int j = 0; j < DOUT; j++) {
        float z = g_s[node * DOUT + j]
                + g_agg1[node * DOUT + j] * inv
                + ind * Wn1[DH * DOUT + j];
        v[j] = z;
        nrm += z * z;
    }
    float rinv = 1.f / (sqrtf(nrm) + EPS);
    float mx = -1e30f;
    #pragma unroll
    for (int j = 0; j < DOUT; j++) { v[j] *= rinv; mx = fmaxf(mx, v[j]); }
    float se = 0.f;
    #pragma unroll
    for (int j = 0; j < DOUT; j++) se += __expf(v[j] - mx);
    float lse = mx + logf(se);
    #pragma unroll
    for (int j = 0; j < DOUT; j++) out[node * DOUT + j] = v[j] - lse;
}

// ---------------- launch ----------------
extern "C" void kernel_launch(void* const* d_in, const int* in_sizes, int n_in,
                              void* d_out, int out_size) {
    const float* x   = (const float*)d_in[0];
    const int*   ei  = (const int*)d_in[1];
    const float* Ws0 = (const float*)d_in[2];
    const float* Wn0 = (const float*)d_in[3];
    const float* Ws1 = (const float*)d_in[4];
    const float* Wn1 = (const float*)d_in[5];
    float* out = (float*)d_out;

    const int* src = ei;
    const int* dst = ei + EE;

    zero_deg_kernel<<<(NN + 255) / 256, 256>>>();
    count_kernel<<<(EE + 255) / 256, 256>>>(dst);
    scan_kernel<<<1, 1024>>>();
    fill_kernel<<<(EE + 255) / 256, 256>>>(src, dst);

    fused0_kernel<<<NN, 128>>>(x, Ws0, Wn0, Ws1, Wn1);

    agg1_kernel<<<(NN * DOUT + 255) / 256, 256>>>();
    final_kernel<<<(NN + 255) / 256, 256>>>(Wn1, out);
}

// round 3
// speedup vs baseline: 1.2624x; 1.2624x over previous
#include <cuda_runtime.h>
#include <math.h>

#define NN   50000
#define EE   800000
#define DIN  64
#define DH   128
#define DOUT 10
#define EPS  1e-8f

#define NPB  32            // nodes per block in transform kernel
#define TBLK ((NN + NPB - 1) / NPB)   // 1563

typedef unsigned long long ull;

// ---------------- scratch ----------------
__device__ int   g_degi[NN];
__device__ float g_deg[NN];
__device__ int   g_rowptr[NN + 1];
__device__ int   g_cursor[NN];
__device__ int   g_csrsrc[EE];
__device__ float g_agg0[NN * DIN];
__device__ float g_s[NN * DOUT];
__device__ float g_t[NN * DOUT];
__device__ float g_agg1[NN * DOUT];

// ---------------- f32x2 helpers ----------------
__device__ __forceinline__ ull fma2(ull a, ull b, ull c) {
    ull d;
    asm("fma.rn.f32x2 %0, %1, %2, %3;" : "=l"(d) : "l"(a), "l"(b), "l"(c));
    return d;
}
__device__ __forceinline__ ull pack2(float lo, float hi) {
    ull d;
    asm("mov.b64 %0, {%1, %2};" : "=l"(d) : "f"(lo), "f"(hi));
    return d;
}
__device__ __forceinline__ void unpack2(ull v, float& lo, float& hi) {
    asm("mov.b64 {%0, %1}, %2;" : "=f"(lo), "=f"(hi) : "l"(v));
}

// ---------------- CSR build ----------------
__global__ void zero_deg_kernel() {
    int i = blockIdx.x * blockDim.x + threadIdx.x;
    if (i < NN) g_degi[i] = 0;
}

__global__ void count_kernel(const int* __restrict__ dst) {
    int e = blockIdx.x * blockDim.x + threadIdx.x;
    if (e < EE) atomicAdd(&g_degi[dst[e]], 1);
}

__global__ void scan_kernel() {
    __shared__ int warp_sums[32];
    const int T = 1024;
    int tid = threadIdx.x;
    int per = (NN + T - 1) / T;
    int start = tid * per;
    int end = start + per; if (end > NN) end = NN;
    int local = 0;
    if (start < NN)
        for (int i = start; i < end; i++) local += g_degi[i];

    int lane = tid & 31, wid = tid >> 5;
    int v = local;
    #pragma unroll
    for (int o = 1; o < 32; o <<= 1) {
        int u = __shfl_up_sync(0xFFFFFFFFu, v, o);
        if (lane >= o) v += u;
    }
    if (lane == 31) warp_sums[wid] = v;
    __syncthreads();
    if (wid == 0) {
        int w = warp_sums[lane];
        #pragma unroll
        for (int o = 1; o < 32; o <<= 1) {
            int u = __shfl_up_sync(0xFFFFFFFFu, w, o);
            if (lane >= o) w += u;
        }
        warp_sums[lane] = w;
    }
    __syncthreads();
    int excl = v - local + (wid > 0 ? warp_sums[wid - 1] : 0);
    if (start < NN) {
        int run = excl;
        for (int i = start; i < end; i++) {
            g_rowptr[i] = run;
            g_cursor[i] = run;
            g_deg[i] = (float)g_degi[i];
            run += g_degi[i];
        }
    }
    if (tid == 0) g_rowptr[NN] = warp_sums[31];
}

__global__ void fill_kernel(const int* __restrict__ src, const int* __restrict__ dst) {
    int e = blockIdx.x * blockDim.x + threadIdx.x;
    if (e < EE) {
        int d = dst[e];
        int p = atomicAdd(&g_cursor[d], 1);
        g_csrsrc[p] = src[e];
    }
}

// ---------------- layer 0 aggregation: warp per node ----------------
__global__ void agg0_kernel(const float* __restrict__ x) {
    int node = blockIdx.x * (blockDim.x >> 5) + (threadIdx.x >> 5);
    if (node >= NN) return;
    int lane = threadIdx.x & 31;
    int beg = g_rowptr[node], end = g_rowptr[node + 1];
    float ax = 0.f, ay = 0.f;
    for (int j = beg; j < end; j++) {
        int s = g_csrsrc[j];
        float2 v = *(const float2*)(x + (size_t)s * DIN + lane * 2);
        ax += v.x; ay += v.y;
    }
    float2 o; o.x = ax; o.y = ay;
    *(float2*)(g_agg0 + (size_t)node * DIN + lane * 2) = o;
}

// ---------------- transform: 32 nodes/block, register-tiled, FFMA2 ----------------
// Dynamic smem layout:
//   sh_s : float2[NPB * 65]   (self,  duplicated {v,v})
//   sh_n : float2[NPB * 65]   (neigh, duplicated {v,v})
//   shW1 : float [128 * 20]   (W_self1 | W_neigh1 interleaved per row)
//   sh_h : float [NPB * 132]  (hidden activations, padded stride)
__global__ void __launch_bounds__(128) transform_kernel(
    const float* __restrict__ x,
    const float* __restrict__ Ws0,   // (65,128)
    const float* __restrict__ Wn0,   // (65,128)
    const float* __restrict__ Ws1,   // (129,10)
    const float* __restrict__ Wn1)   // (129,10)
{
    extern __shared__ char dyn[];
    float2* sh_s = (float2*)dyn;
    float2* sh_n = sh_s + NPB * 65;
    float*  shW1 = (float*)(sh_n + NPB * 65);
    float*  sh_h = shW1 + 128 * 20;

    const int tid = threadIdx.x;
    const int nb  = blockIdx.x * NPB;

    // ---- stage self / neigh (duplicated) ----
    for (int idx = tid; idx < NPB * DIN; idx += 128) {
        int node = idx >> 6;
        int k    = idx & 63;
        int gn   = nb + node;
        float vs = 0.f, vn = 0.f;
        if (gn < NN) {
            vs = x[(size_t)gn * DIN + k];
            float degv = g_deg[gn];
            float inv = 1.f / fmaxf(degv, 1.f);
            vn = g_agg0[(size_t)gn * DIN + k] * inv;
        }
        sh_s[node * 65 + k] = make_float2(vs, vs);
        sh_n[node * 65 + k] = make_float2(vn, vn);
    }
    if (tid < NPB) {
        int gn = nb + tid;
        float one = 0.f, ind = 0.f;
        if (gn < NN) { one = 1.f; ind = (g_deg[gn] > 0.f) ? 1.f : 0.f; }
        sh_s[tid * 65 + DIN] = make_float2(one, one);
        sh_n[tid * 65 + DIN] = make_float2(ind, ind);
    }
    // ---- stage W1 ----
    for (int idx = tid; idx < 128 * 20; idx += 128) {
        int k = idx / 20;
        int j = idx - k * 20;
        shW1[idx] = (j < 10) ? Ws1[k * DOUT + j] : Wn1[k * DOUT + (j - 10)];
    }
    __syncthreads();

    // ---- main GEMM: thread = 4 nodes (a*4..a*4+3) x 8 cols (pairs {2cg,2cg+1}+32p) ----
    const int a  = tid >> 4;   // 0..7
    const int cg = tid & 15;   // 0..15

    ull acc[4][4];
    #pragma unroll
    for (int i = 0; i < 4; i++)
        #pragma unroll
        for (int p = 0; p < 4; p++) acc[i][p] = 0ull;

    const ull* s_base = (const ull*)(sh_s + (a * 4) * 65);
    const ull* n_base = (const ull*)(sh_n + (a * 4) * 65);

    #pragma unroll 1
    for (int k = 0; k <= DIN; k++) {
        const ull* wsp = (const ull*)(Ws0 + k * DH) + cg;
        const ull* wnp = (const ull*)(Wn0 + k * DH) + cg;
        ull ws[4], wn[4];
        #pragma unroll
        for (int p = 0; p < 4; p++) { ws[p] = wsp[16 * p]; wn[p] = wnp[16 * p]; }
        ull s2[4], n2[4];
        #pragma unroll
        for (int i = 0; i < 4; i++) { s2[i] = s_base[i * 65 + k]; n2[i] = n_base[i * 65 + k]; }
        #pragma unroll
        for (int i = 0; i < 4; i++)
            #pragma unroll
            for (int p = 0; p < 4; p++) {
                acc[i][p] = fma2(s2[i], ws[p], acc[i][p]);
                acc[i][p] = fma2(n2[i], wn[p], acc[i][p]);
            }
    }

    // ---- norm + relu -> sh_h ----
    float vlo[4][4], vhi[4][4];
    float tot[4];
    #pragma unroll
    for (int i = 0; i < 4; i++) {
        float sq = 0.f;
        #pragma unroll
        for (int p = 0; p < 4; p++) {
            unpack2(acc[i][p], vlo[i][p], vhi[i][p]);
            sq += vlo[i][p] * vlo[i][p] + vhi[i][p] * vhi[i][p];
        }
        tot[i] = sq;
    }
    #pragma unroll
    for (int o = 1; o < 16; o <<= 1) {
        #pragma unroll
        for (int i = 0; i < 4; i++)
            tot[i] += __shfl_xor_sync(0xFFFFFFFFu, tot[i], o);
    }
    #pragma unroll
    for (int i = 0; i < 4; i++) {
        float rinv = 1.f / (sqrtf(tot[i]) + EPS);
        int node = a * 4 + i;
        #pragma unroll
        for (int p = 0; p < 4; p++) {
            int col = 2 * cg + 32 * p;
            float2 hv;
            hv.x = fmaxf(vlo[i][p] * rinv, 0.f);
            hv.y = fmaxf(vhi[i][p] * rinv, 0.f);
            *(float2*)(sh_h + node * 132 + col) = hv;
        }
    }
    __syncthreads();

    // ---- layer-1 projection: thread = (node = tid>>2, strip = tid&3) ----
    {
        const int n = tid >> 2;     // 0..31
        const int s = tid & 3;      // k-strip
        ull pa[10];
        #pragma unroll
        for (int jp = 0; jp < 10; jp++) pa[jp] = 0ull;

        const float* hrow = sh_h + n * 132 + s * 32;
        #pragma unroll 4
        for (int k0 = 0; k0 < 32; k0++) {
            float hv = hrow[k0];
            ull h2 = pack2(hv, hv);
            const ull* Wp = (const ull*)(shW1 + (s * 32 + k0) * 20);
            #pragma unroll
            for (int jp = 0; jp < 10; jp++)
                pa[jp] = fma2(h2, Wp[jp], pa[jp]);
        }
        float pj[20];
        #pragma unroll
        for (int jp = 0; jp < 10; jp++) unpack2(pa[jp], pj[2 * jp], pj[2 * jp + 1]);
        #pragma unroll
        for (int j = 0; j < 20; j++) {
            pj[j] += __shfl_xor_sync(0xFFFFFFFFu, pj[j], 1);
            pj[j] += __shfl_xor_sync(0xFFFFFFFFu, pj[j], 2);
        }
        int gn = nb + n;
        if (gn < NN) {
            #pragma unroll
            for (int j = 0; j < 20; j++) {
                if (j >= s * 5 && j < s * 5 + 5) {
                    if (j < 10)
                        g_s[gn * DOUT + j] = pj[j] + Ws1[DH * DOUT + j];
                    else
                        g_t[gn * DOUT + (j - 10)] = pj[j];
                }
            }
        }
    }
}

// ---------------- layer 1 aggregation in output space ----------------
__global__ void agg1_kernel() {
    int idx = blockIdx.x * blockDim.x + threadIdx.x;
    if (idx >= NN * DOUT) return;
    int node = idx / DOUT;
    int j = idx - node * DOUT;
    int beg = g_rowptr[node], end = g_rowptr[node + 1];
    float acc = 0.f;
    for (int p = beg; p < end; p++) {
        int s = g_csrsrc[p];
        acc += g_t[s * DOUT + j];
    }
    g_agg1[idx] = acc;
}

// ---------------- final: combine, projective norm, log-softmax ----------------
__global__ void final_kernel(const float* __restrict__ Wn1, float* __restrict__ out) {
    int node = blockIdx.x * blockDim.x + threadIdx.x;
    if (node >= NN) return;
    float degv = g_deg[node];
    float inv = 1.f / fmaxf(degv, 1.f);
    float ind = (degv > 0.f) ? 1.f : 0.f;
    float v[DOUT];
    float nrm = 0.f;
    #pragma unroll
    for (int j = 0; j < DOUT; j++) {
        float z = g_s[node * DOUT + j]
                + g_agg1[node * DOUT + j] * inv
                + ind * Wn1[DH * DOUT + j];
        v[j] = z;
        nrm += z * z;
    }
    float rinv = 1.f / (sqrtf(nrm) + EPS);
    float mx = -1e30f;
    #pragma unroll
    for (int j = 0; j < DOUT; j++) { v[j] *= rinv; mx = fmaxf(mx, v[j]); }
    float se = 0.f;
    #pragma unroll
    for (int j = 0; j < DOUT; j++) se += __expf(v[j] - mx);
    float lse = mx + logf(se);
    #pragma unroll
    for (int j = 0; j < DOUT; j++) out[node * DOUT + j] = v[j] - lse;
}

// ---------------- launch ----------------
extern "C" void kernel_launch(void* const* d_in, const int* in_sizes, int n_in,
                              void* d_out, int out_size) {
    const float* x   = (const float*)d_in[0];
    const int*   ei  = (const int*)d_in[1];
    const float* Ws0 = (const float*)d_in[2];
    const float* Wn0 = (const float*)d_in[3];
    const float* Ws1 = (const float*)d_in[4];
    const float* Wn1 = (const float*)d_in[5];
    float* out = (float*)d_out;

    const int* src = ei;
    const int* dst = ei + EE;

    // transform kernel dynamic smem: sh_s + sh_n + shW1 + sh_h
    const int SMEM = NPB * 65 * 8 * 2 + 128 * 20 * 4 + NPB * 132 * 4;  // 60416 B
    static int attr_set = 0;
    cudaFuncSetAttribute(transform_kernel, cudaFuncAttributeMaxDynamicSharedMemorySize, SMEM);
    (void)attr_set;

    zero_deg_kernel<<<(NN + 255) / 256, 256>>>();
    count_kernel<<<(EE + 255) / 256, 256>>>(dst);
    scan_kernel<<<1, 1024>>>();
    fill_kernel<<<(EE + 255) / 256, 256>>>(src, dst);

    agg0_kernel<<<(NN * 32 + 255) / 256, 256>>>(x);
    transform_kernel<<<TBLK, 128, SMEM>>>(x, Ws0, Wn0, Ws1, Wn1);

    agg1_kernel<<<(NN * DOUT + 255) / 256, 256>>>();
    final_kernel<<<(NN + 255) / 256, 256>>>(Wn1, out);
}

// round 4
// speedup vs baseline: 1.9943x; 1.5798x over previous
#include <cuda_runtime.h>
#include <math.h>

#define NN   50000
#define EE   800000
#define DIN  64
#define DH   128
#define DOUT 10
#define EPS  1e-8f

#define NPB  32
#define TBLK ((NN + NPB - 1) / NPB)

#define SCB  1024
#define NSB  ((NN + SCB - 1) / SCB)   // 49

#define ONB  25                        // nodes per output block

typedef unsigned long long ull;

// ---------------- scratch ----------------
__device__ int   g_degi[NN];
__device__ float g_deg[NN];
__device__ int   g_rowptr[NN + 1];
__device__ int   g_cursor[NN];
__device__ int   g_csrsrc[EE];
__device__ float g_agg0[NN * DIN];
__device__ float g_s[NN * DOUT];
__device__ float g_t[NN * DOUT];
__device__ int   g_bsum[64];
__device__ int   g_boff[64];

// ---------------- f32x2 helpers ----------------
__device__ __forceinline__ ull fma2(ull a, ull b, ull c) {
    ull d;
    asm("fma.rn.f32x2 %0, %1, %2, %3;" : "=l"(d) : "l"(a), "l"(b), "l"(c));
    return d;
}
__device__ __forceinline__ ull dup2(float v) {
    ull d;
    asm("mov.b64 %0, {%1, %1};" : "=l"(d) : "f"(v));
    return d;
}
__device__ __forceinline__ void unpack2(ull v, float& lo, float& hi) {
    asm("mov.b64 {%0, %1}, %2;" : "=f"(lo), "=f"(hi) : "l"(v));
}

// ---------------- CSR build ----------------
__global__ void zero_deg_kernel() {
    int i = blockIdx.x * blockDim.x + threadIdx.x;
    if (i < NN) g_degi[i] = 0;
}

__global__ void count_kernel(const int* __restrict__ dst) {
    int e = blockIdx.x * blockDim.x + threadIdx.x;
    if (e < EE) atomicAdd(&g_degi[dst[e]], 1);
}

// phase A: per-block sums
__global__ void scanA_kernel() {
    __shared__ int ws[32];
    int tid = threadIdx.x;
    int i = blockIdx.x * SCB + tid;
    int v = (i < NN) ? g_degi[i] : 0;
    #pragma unroll
    for (int o = 16; o > 0; o >>= 1) v += __shfl_down_sync(0xFFFFFFFFu, v, o);
    int lane = tid & 31, wid = tid >> 5;
    if (lane == 0) ws[wid] = v;
    __syncthreads();
    if (wid == 0) {
        int t = ws[lane];
        #pragma unroll
        for (int o = 16; o > 0; o >>= 1) t += __shfl_down_sync(0xFFFFFFFFu, t, o);
        if (lane == 0) g_bsum[blockIdx.x] = t;
    }
}

// phase B: scan NSB block sums (64 threads)
__global__ void scanB_kernel() {
    __shared__ int t0;
    int tid = threadIdx.x;
    int lane = tid & 31, w = tid >> 5;
    int v = (tid < NSB) ? g_bsum[tid] : 0;
    int inc = v;
    #pragma unroll
    for (int o = 1; o < 32; o <<= 1) {
        int u = __shfl_up_sync(0xFFFFFFFFu, inc, o);
        if (lane >= o) inc += u;
    }
    if (tid == 31) t0 = inc;
    __syncthreads();
    if (w == 1) inc += t0;
    g_boff[tid] = inc - v;
}

// phase C: block scan + global offset, write rowptr/cursor/deg
__global__ void scanC_kernel() {
    __shared__ int wsum[32];
    int tid = threadIdx.x;
    int i = blockIdx.x * SCB + tid;
    int v = (i < NN) ? g_degi[i] : 0;
    int lane = tid & 31, wid = tid >> 5;
    int inc = v;
    #pragma unroll
    for (int o = 1; o < 32; o <<= 1) {
        int u = __shfl_up_sync(0xFFFFFFFFu, inc, o);
        if (lane >= o) inc += u;
    }
    if (lane == 31) wsum[wid] = inc;
    __syncthreads();
    if (wid == 0) {
        int t = wsum[lane];
        #pragma unroll
        for (int o = 1; o < 32; o <<= 1) {
            int u = __shfl_up_sync(0xFFFFFFFFu, t, o);
            if (lane >= o) t += u;
        }
        wsum[lane] = t;
    }
    __syncthreads();
    int excl = inc - v + (wid > 0 ? wsum[wid - 1] : 0) + g_boff[blockIdx.x];
    if (i < NN) {
        g_rowptr[i] = excl;
        g_cursor[i] = excl;
        g_deg[i] = (float)v;
        if (i == NN - 1) g_rowptr[NN] = excl + v;
    }
}

__global__ void fill_kernel(const int* __restrict__ src, const int* __restrict__ dst) {
    int e = blockIdx.x * blockDim.x + threadIdx.x;
    if (e < EE) {
        int d = dst[e];
        int p = atomicAdd(&g_cursor[d], 1);
        g_csrsrc[p] = src[e];
    }
}

// ---------------- layer 0 aggregation: warp per node, 4-batched ----------------
__global__ void agg0_kernel(const float* __restrict__ x) {
    int node = blockIdx.x * (blockDim.x >> 5) + (threadIdx.x >> 5);
    if (node >= NN) return;
    int lane = threadIdx.x & 31;
    int beg = g_rowptr[node], end = g_rowptr[node + 1];
    float ax = 0.f, ay = 0.f, bx = 0.f, by = 0.f;
    int j = beg;
    for (; j + 4 <= end; j += 4) {
        int s0 = g_csrsrc[j], s1 = g_csrsrc[j + 1], s2 = g_csrsrc[j + 2], s3 = g_csrsrc[j + 3];
        float2 v0 = *(const float2*)(x + (size_t)s0 * DIN + lane * 2);
        float2 v1 = *(const float2*)(x + (size_t)s1 * DIN + lane * 2);
        float2 v2 = *(const float2*)(x + (size_t)s2 * DIN + lane * 2);
        float2 v3 = *(const float2*)(x + (size_t)s3 * DIN + lane * 2);
        ax += v0.x; ay += v0.y;
        bx += v1.x; by += v1.y;
        ax += v2.x; ay += v2.y;
        bx += v3.x; by += v3.y;
    }
    for (; j < end; j++) {
        int s = g_csrsrc[j];
        float2 v = *(const float2*)(x + (size_t)s * DIN + lane * 2);
        ax += v.x; ay += v.y;
    }
    float2 o; o.x = ax + bx; o.y = ay + by;
    *(float2*)(g_agg0 + (size_t)node * DIN + lane * 2) = o;
}

// ---------------- transform: 32 nodes/block, LDG.128 weights, FFMA2 ----------------
// dyn smem: sh_s[NPB*66] | sh_n[NPB*66] | shW1[128*20] | sh_h[NPB*132]
__global__ void __launch_bounds__(128) transform_kernel(
    const float* __restrict__ x,
    const float* __restrict__ Ws0,   // (65,128)
    const float* __restrict__ Wn0,   // (65,128)
    const float* __restrict__ Ws1,   // (129,10)
    const float* __restrict__ Wn1)   // (129,10)
{
    extern __shared__ char dyn[];
    float* sh_s = (float*)dyn;
    float* sh_n = sh_s + NPB * 66;
    float* shW1 = sh_n + NPB * 66;
    float* sh_h = shW1 + 128 * 20;

    const int tid = threadIdx.x;
    const int nb  = blockIdx.x * NPB;

    // ---- stage self / neigh ----
    for (int idx = tid; idx < NPB * DIN; idx += 128) {
        int node = idx >> 6;
        int k    = idx & 63;
        int gn   = nb + node;
        float vs = 0.f, vn = 0.f;
        if (gn < NN) {
            vs = x[(size_t)gn * DIN + k];
            float degv = g_deg[gn];
            vn = g_agg0[(size_t)gn * DIN + k] * (1.f / fmaxf(degv, 1.f));
        }
        sh_s[node * 66 + k] = vs;
        sh_n[node * 66 + k] = vn;
    }
    if (tid < NPB) {
        int gn = nb + tid;
        sh_s[tid * 66 + DIN] = (gn < NN) ? 1.f : 0.f;
        sh_n[tid * 66 + DIN] = (gn < NN && g_deg[gn] > 0.f) ? 1.f : 0.f;
    }
    for (int idx = tid; idx < 128 * 20; idx += 128) {
        int k = idx / 20;
        int j = idx - k * 20;
        shW1[idx] = (j < 10) ? Ws1[k * DOUT + j] : Wn1[k * DOUT + (j - 10)];
    }
    __syncthreads();

    // ---- GEMM: thread = 4 nodes x 8 cols (float4 groups at 4cg and 4cg+64) ----
    const int a  = tid >> 4;   // 0..7 -> nodes a*4 .. a*4+3
    const int cg = tid & 15;   // 0..15 -> cols 4cg..4cg+3 and +64

    ull acc[4][2][2];
    #pragma unroll
    for (int i = 0; i < 4; i++)
        #pragma unroll
        for (int p = 0; p < 2; p++) { acc[i][p][0] = 0ull; acc[i][p][1] = 0ull; }

    const float* srow = sh_s + (a * 4) * 66;
    const float* nrow = sh_n + (a * 4) * 66;

    #pragma unroll 2
    for (int k = 0; k <= DIN; k++) {
        ulonglong2 ws0v = *(const ulonglong2*)(Ws0 + k * DH + 4 * cg);
        ulonglong2 ws1v = *(const ulonglong2*)(Ws0 + k * DH + 4 * cg + 64);
        ulonglong2 wn0v = *(const ulonglong2*)(Wn0 + k * DH + 4 * cg);
        ulonglong2 wn1v = *(const ulonglong2*)(Wn0 + k * DH + 4 * cg + 64);
        #pragma unroll
        for (int i = 0; i < 4; i++) {
            ull s2 = dup2(srow[i * 66 + k]);
            ull n2 = dup2(nrow[i * 66 + k]);
            acc[i][0][0] = fma2(s2, ws0v.x, acc[i][0][0]);
            acc[i][0][1] = fma2(s2, ws0v.y, acc[i][0][1]);
            acc[i][1][0] = fma2(s2, ws1v.x, acc[i][1][0]);
            acc[i][1][1] = fma2(s2, ws1v.y, acc[i][1][1]);
            acc[i][0][0] = fma2(n2, wn0v.x, acc[i][0][0]);
            acc[i][0][1] = fma2(n2, wn0v.y, acc[i][0][1]);
            acc[i][1][0] = fma2(n2, wn1v.x, acc[i][1][0]);
            acc[i][1][1] = fma2(n2, wn1v.y, acc[i][1][1]);
        }
    }

    // ---- norm + relu -> sh_h ----
    float lo[4][2][2], hi[4][2][2];
    float tot[4];
    #pragma unroll
    for (int i = 0; i < 4; i++) {
        float sq = 0.f;
        #pragma unroll
        for (int p = 0; p < 2; p++)
            #pragma unroll
            for (int h = 0; h < 2; h++) {
                unpack2(acc[i][p][h], lo[i][p][h], hi[i][p][h]);
                sq += lo[i][p][h] * lo[i][p][h] + hi[i][p][h] * hi[i][p][h];
            }
        tot[i] = sq;
    }
    #pragma unroll
    for (int o = 1; o < 16; o <<= 1) {
        #pragma unroll
        for (int i = 0; i < 4; i++)
            tot[i] += __shfl_xor_sync(0xFFFFFFFFu, tot[i], o);
    }
    #pragma unroll
    for (int i = 0; i < 4; i++) {
        float rinv = 1.f / (sqrtf(tot[i]) + EPS);
        int node = a * 4 + i;
        #pragma unroll
        for (int p = 0; p < 2; p++) {
            float4 hv;
            hv.x = fmaxf(lo[i][p][0] * rinv, 0.f);
            hv.y = fmaxf(hi[i][p][0] * rinv, 0.f);
            hv.z = fmaxf(lo[i][p][1] * rinv, 0.f);
            hv.w = fmaxf(hi[i][p][1] * rinv, 0.f);
            *(float4*)(sh_h + node * 132 + 4 * cg + 64 * p) = hv;
        }
    }
    __syncthreads();

    // ---- layer-1 projection: thread = (node = tid>>2, strip = tid&3) ----
    {
        const int n = tid >> 2;
        const int s = tid & 3;
        ull pa[10];
        #pragma unroll
        for (int jp = 0; jp < 10; jp++) pa[jp] = 0ull;

        const float* hrow = sh_h + n * 132 + s * 32;
        #pragma unroll 4
        for (int k0 = 0; k0 < 32; k0++) {
            ull h2 = dup2(hrow[k0]);
            const ull* Wp = (const ull*)(shW1 + (s * 32 + k0) * 20);
            #pragma unroll
            for (int jp = 0; jp < 10; jp++)
                pa[jp] = fma2(h2, Wp[jp], pa[jp]);
        }
        float pj[20];
        #pragma unroll
        for (int jp = 0; jp < 10; jp++) unpack2(pa[jp], pj[2 * jp], pj[2 * jp + 1]);
        #pragma unroll
        for (int j = 0; j < 20; j++) {
            pj[j] += __shfl_xor_sync(0xFFFFFFFFu, pj[j], 1);
            pj[j] += __shfl_xor_sync(0xFFFFFFFFu, pj[j], 2);
        }
        int gn = nb + n;
        if (gn < NN) {
            #pragma unroll
            for (int j = 0; j < 20; j++) {
                if (j >= s * 5 && j < s * 5 + 5) {
                    if (j < 10)
                        g_s[gn * DOUT + j] = pj[j] + Ws1[DH * DOUT + j];
                    else
                        g_t[gn * DOUT + (j - 10)] = pj[j];
                }
            }
        }
    }
}

// ---------------- fused: layer-1 aggregation + combine + norm + log-softmax ----
__global__ void __launch_bounds__(256) output_kernel(
    const float* __restrict__ Wn1, float* __restrict__ out)
{
    __shared__ float sz[ONB * DOUT];
    int tid = threadIdx.x;
    if (tid < ONB * DOUT) {
        int nloc = tid / DOUT;
        int j = tid - nloc * DOUT;
        int node = blockIdx.x * ONB + nloc;
        if (node < NN) {
            int beg = g_rowptr[node], end = g_rowptr[node + 1];
            float acc = 0.f;
            int p = beg;
            for (; p + 2 <= end; p += 2) {
                int s0 = g_csrsrc[p], s1 = g_csrsrc[p + 1];
                acc += g_t[s0 * DOUT + j] + g_t[s1 * DOUT + j];
            }
            if (p < end) acc += g_t[g_csrsrc[p] * DOUT + j];
            float degv = (float)(end - beg);
            float inv = 1.f / fmaxf(degv, 1.f);
            float ind = (degv > 0.f) ? 1.f : 0.f;
            sz[nloc * DOUT + j] = g_s[node * DOUT + j] + acc * inv + ind * Wn1[DH * DOUT + j];
        }
    }
    __syncthreads();
    if (tid < ONB) {
        int node = blockIdx.x * ONB + tid;
        if (node < NN) {
            float v[DOUT];
            float nrm = 0.f;
            #pragma unroll
            for (int j = 0; j < DOUT; j++) { v[j] = sz[tid * DOUT + j]; nrm += v[j] * v[j]; }
            float rinv = 1.f / (sqrtf(nrm) + EPS);
            float mx = -1e30f;
            #pragma unroll
            for (int j = 0; j < DOUT; j++) { v[j] *= rinv; mx = fmaxf(mx, v[j]); }
            float se = 0.f;
            #pragma unroll
            for (int j = 0; j < DOUT; j++) se += __expf(v[j] - mx);
            float lse = mx + logf(se);
            #pragma unroll
            for (int j = 0; j < DOUT; j++) out[node * DOUT + j] = v[j] - lse;
        }
    }
}

// ---------------- launch ----------------
extern "C" void kernel_launch(void* const* d_in, const int* in_sizes, int n_in,
                              void* d_out, int out_size) {
    const float* x   = (const float*)d_in[0];
    const int*   ei  = (const int*)d_in[1];
    const float* Ws0 = (const float*)d_in[2];
    const float* Wn0 = (const float*)d_in[3];
    const float* Ws1 = (const float*)d_in[4];
    const float* Wn1 = (const float*)d_in[5];
    float* out = (float*)d_out;

    const int* src = ei;
    const int* dst = ei + EE;

    const int SMEM = (NPB * 66 * 2 + 128 * 20 + NPB * 132) * 4;  // 44032 B
    cudaFuncSetAttribute(transform_kernel, cudaFuncAttributeMaxDynamicSharedMemorySize, SMEM);

    zero_deg_kernel<<<(NN + 255) / 256, 256>>>();
    count_kernel<<<(EE + 255) / 256, 256>>>(dst);
    scanA_kernel<<<NSB, SCB>>>();
    scanB_kernel<<<1, 64>>>();
    scanC_kernel<<<NSB, SCB>>>();
    fill_kernel<<<(EE + 255) / 256, 256>>>(src, dst);

    agg0_kernel<<<(NN * 32 + 255) / 256, 256>>>(x);
    transform_kernel<<<TBLK, 128, SMEM>>>(x, Ws0, Wn0, Ws1, Wn1);

    output_kernel<<<(NN + ONB - 1) / ONB, 256>>>(Wn1, out);
}